// round 2
// baseline (speedup 1.0000x reference)
#include <cuda_runtime.h>

// out = 0.9*p + 0.1 * softmax(-4 p p^T) @ p     (N=16384, D=64, fp32)
// Flash-attention formulation, SIMT fp32 with packed f32x2 FMA.

#define DDIM     64
#define NROWS    64      // query rows per block
#define SPLIT    4       // key-range split per row
#define NTHREADS 256     // NROWS * SPLIT
#define TK       64      // keys per smem tile

typedef unsigned long long u64;

__device__ __forceinline__ u64 pack2(float x, float y) {
    u64 r; asm("mov.b64 %0, {%1, %2};" : "=l"(r) : "f"(x), "f"(y)); return r;
}
__device__ __forceinline__ void unpack2(u64 v, float &x, float &y) {
    asm("mov.b64 {%0, %1}, %2;" : "=f"(x), "=f"(y) : "l"(v));
}
__device__ __forceinline__ void fma2(u64 &d, u64 a, u64 b) {
    asm("fma.rn.f32x2 %0, %1, %2, %0;" : "+l"(d) : "l"(a), "l"(b));
}
__device__ __forceinline__ void mul2(u64 &d, u64 a) {
    asm("mul.rn.f32x2 %0, %0, %1;" : "+l"(d) : "l"(a));
}
__device__ __forceinline__ u64 add2(u64 a, u64 b) {
    u64 r; asm("add.rn.f32x2 %0, %1, %2;" : "=l"(r) : "l"(a), "l"(b)); return r;
}

__global__ __launch_bounds__(NTHREADS, 1)
void gradattn_kernel(const float* __restrict__ p, float* __restrict__ out, int N) {
    // Double-buffered K tile: 2 x 64 keys x 64 floats = 32 KB (as 16B vectors).
    __shared__ ulonglong2 kt[2][TK][16];
    __shared__ float mbuf[SPLIT][NROWS];
    __shared__ float lbuf[SPLIT][NROWS];
    __shared__ float Lbuf[NROWS];

    const int tid  = threadIdx.x;
    const int s    = tid >> 6;          // key subgroup 0..3 (warp-uniform)
    const int r    = tid & 63;          // row within block
    const int grow = blockIdx.x * NROWS + r;

    // Load this thread's query row into registers, packed as f32x2.
    u64 q2[32];
    {
        const u64* qp = (const u64*)(p + (size_t)grow * DDIM);
        #pragma unroll
        for (int i = 0; i < 32; i++) q2[i] = qp[i];
    }

    u64 acc2[32];
    #pragma unroll
    for (int i = 0; i < 32; i++) acc2[i] = 0ULL;   // bits of (0.0f, 0.0f)
    float m = -1e30f;
    float l = 0.0f;

    const ulonglong2* pg = (const ulonglong2*)p;   // 16B-vector view of p
    const int NT = N / TK;

    // Preload tile 0 (coalesced: 256 threads x 4 x 16B).
    {
        ulonglong2* dst = (ulonglong2*)kt[0];
        #pragma unroll
        for (int u = 0; u < 4; u++)
            dst[tid + u * NTHREADS] = pg[tid + u * NTHREADS];
    }
    __syncthreads();

    for (int t = 0; t < NT; t++) {
        const int cur = t & 1;
        const bool hasnext = (t + 1 < NT);
        ulonglong2 pf0, pf1, pf2, pf3;
        if (hasnext) {
            const ulonglong2* src = pg + (size_t)(t + 1) * (TK * 16);
            pf0 = src[tid];
            pf1 = src[tid + 256];
            pf2 = src[tid + 512];
            pf3 = src[tid + 768];
        }

        const ulonglong2 (*kb)[16] = kt[cur];

        // ---- scores for this thread's 16 keys of the tile ----
        float tv[16];
        #pragma unroll
        for (int kk = 0; kk < 16; kk++) {
            const ulonglong2* krow = kb[s * 16 + kk];   // broadcast within warp
            u64 da = 0ULL, db = 0ULL;
            #pragma unroll
            for (int i = 0; i < 16; i += 2) {
                ulonglong2 kv0 = krow[i];
                ulonglong2 kv1 = krow[i + 1];
                fma2(da, q2[2 * i],     kv0.x);
                fma2(db, q2[2 * i + 1], kv0.y);
                fma2(da, q2[2 * i + 2], kv1.x);
                fma2(db, q2[2 * i + 3], kv1.y);
            }
            u64 dsum = add2(da, db);
            float x, y; unpack2(dsum, x, y);
            tv[kk] = -4.0f * (x + y);                   // logit = -scores
        }

        // ---- online softmax: chunk max, rare rescale ----
        float mc = tv[0];
        #pragma unroll
        for (int kk = 1; kk < 16; kk++) mc = fmaxf(mc, tv[kk]);
        if (mc > m) {
            float sc = __expf(m - mc);
            m = mc;
            l *= sc;
            u64 sc2 = pack2(sc, sc);
            #pragma unroll
            for (int i = 0; i < 32; i++) mul2(acc2[i], sc2);
        }

        // ---- accumulate weighted values ----
        #pragma unroll
        for (int kk = 0; kk < 16; kk++) {
            float w = __expf(tv[kk] - m);
            l += w;
            u64 w2 = pack2(w, w);
            const ulonglong2* krow = kb[s * 16 + kk];
            #pragma unroll
            for (int i = 0; i < 16; i++) {
                ulonglong2 kv = krow[i];
                fma2(acc2[2 * i],     w2, kv.x);
                fma2(acc2[2 * i + 1], w2, kv.y);
            }
        }

        // ---- stage next tile (writes other buffer; safe vs. current reads) ----
        if (hasnext) {
            ulonglong2* dst = (ulonglong2*)kt[cur ^ 1];
            dst[tid]       = pf0;
            dst[tid + 256] = pf1;
            dst[tid + 512] = pf2;
            dst[tid + 768] = pf3;
        }
        __syncthreads();
    }

    // ---- merge the 4 key-split softmax states per row ----
    mbuf[s][r] = m;
    lbuf[s][r] = l;
    __syncthreads();

    const float M = fmaxf(fmaxf(mbuf[0][r], mbuf[1][r]),
                          fmaxf(mbuf[2][r], mbuf[3][r]));
    const float f = __expf(m - M);
    lbuf[s][r] = l * f;               // rescaled partial denominators

    // Overlay merge buffer on the (now dead) K tiles; stride 65 avoids conflicts.
    float* ab = (float*)kt;
    #pragma unroll 1
    for (int sx = 0; sx < SPLIT; sx++) {
        if (s == sx) {
            float* dst = ab + r * 65;
            #pragma unroll
            for (int i = 0; i < 32; i++) {
                float x, y; unpack2(acc2[i], x, y);
                if (sx == 0) { dst[2 * i] = f * x;  dst[2 * i + 1] = f * y; }
                else         { dst[2 * i] += f * x; dst[2 * i + 1] += f * y; }
            }
        }
        __syncthreads();
    }

    if (s == 0)
        Lbuf[r] = lbuf[0][r] + lbuf[1][r] + lbuf[2][r] + lbuf[3][r];
    __syncthreads();

    // ---- epilogue: out = p + 0.1 * (acc/L - p) ----
    const float* pb = p   + (size_t)blockIdx.x * NROWS * DDIM;
    float*       ob = out + (size_t)blockIdx.x * NROWS * DDIM;
    for (int i = tid; i < NROWS * DDIM; i += NTHREADS) {
        int rr = i >> 6, dd = i & 63;
        float pv = pb[i];
        float av = ab[rr * 65 + dd] / Lbuf[rr];
        ob[i] = fmaf(0.1f, av - pv, pv);
    }
}

extern "C" void kernel_launch(void* const* d_in, const int* in_sizes, int n_in,
                              void* d_out, int out_size) {
    const float* p = (const float*)d_in[0];
    float* out = (float*)d_out;
    const int N = in_sizes[0] / DDIM;        // 16384
    gradattn_kernel<<<N / NROWS, NTHREADS>>>(p, out, N);
}

// round 4
// speedup vs baseline: 39.8721x; 39.8721x over previous
#include <cuda_runtime.h>
#include <cuda_bf16.h>
#include <cstdint>

// out = 0.9*p + 0.1 * softmax(-4 p p^T) p    N=16384, D=64, fp32
// FA2-style flash attention with mma.sync bf16 (hi/lo split), cp.async pipeline.

#define D_DIM 64
#define TM    64          // query rows per CTA (4 warps x 16)
#define TN    64          // keys per tile
#define NTH   128
#define PN    (16384*64)

__device__ __nv_bfloat16 g_ph[PN];
__device__ __nv_bfloat16 g_pl[PN];

__device__ __forceinline__ uint32_t smem_u32(const void* p) {
    uint32_t a;
    asm("{ .reg .u64 t; cvta.to.shared.u64 t, %1; cvt.u32.u64 %0, t; }" : "=r"(a) : "l"(p));
    return a;
}
#define SWZ(x) ((x) ^ (((x) >> 3) & 0x70))

#define CP16(dst, src) asm volatile("cp.async.ca.shared.global [%0], [%1], 16;" :: "r"(dst), "l"(src))
#define CP_COMMIT()    asm volatile("cp.async.commit_group;" ::: "memory")
#define CP_WAIT0()     asm volatile("cp.async.wait_group 0;" ::: "memory")

#define LDSM4(r0, r1, r2, r3, a) \
    asm volatile("ldmatrix.sync.aligned.m8n8.x4.shared.b16 {%0,%1,%2,%3}, [%4];" \
        : "=r"(r0), "=r"(r1), "=r"(r2), "=r"(r3) : "r"(a))
#define LDSM4T(r0, r1, r2, r3, a) \
    asm volatile("ldmatrix.sync.aligned.m8n8.x4.trans.shared.b16 {%0,%1,%2,%3}, [%4];" \
        : "=r"(r0), "=r"(r1), "=r"(r2), "=r"(r3) : "r"(a))

__device__ __forceinline__ void mma16816(float* c, const uint32_t a[4], uint32_t b0, uint32_t b1) {
    asm volatile("mma.sync.aligned.m16n8k16.row.col.f32.bf16.bf16.f32 "
        "{%0,%1,%2,%3},{%4,%5,%6,%7},{%8,%9},{%0,%1,%2,%3};"
        : "+f"(c[0]), "+f"(c[1]), "+f"(c[2]), "+f"(c[3])
        : "r"(a[0]), "r"(a[1]), "r"(a[2]), "r"(a[3]), "r"(b0), "r"(b1));
}
__device__ __forceinline__ void mma16816r(float* c, uint32_t a0, uint32_t a1, uint32_t a2, uint32_t a3,
                                          uint32_t b0, uint32_t b1) {
    asm volatile("mma.sync.aligned.m16n8k16.row.col.f32.bf16.bf16.f32 "
        "{%0,%1,%2,%3},{%4,%5,%6,%7},{%8,%9},{%0,%1,%2,%3};"
        : "+f"(c[0]), "+f"(c[1]), "+f"(c[2]), "+f"(c[3])
        : "r"(a0), "r"(a1), "r"(a2), "r"(a3), "r"(b0), "r"(b1));
}
__device__ __forceinline__ float ex2(float x) {
    float r; asm("ex2.approx.ftz.f32 %0, %1;" : "=f"(r) : "f"(x)); return r;
}
__device__ __forceinline__ uint32_t packbf(float lo, float hi) {
    uint32_t r; asm("cvt.rn.bf16x2.f32 %0, %2, %1;" : "=r"(r) : "f"(lo), "f"(hi)); return r;
}

__global__ void prep_kernel(const float* __restrict__ p, int n) {
    int i = blockIdx.x * blockDim.x + threadIdx.x;
    if (i < n) {
        float x = p[i];
        __nv_bfloat16 h = __float2bfloat16(x);
        g_ph[i] = h;
        g_pl[i] = __float2bfloat16(x - __bfloat162float(h));
    }
}

__global__ void __launch_bounds__(NTH, 2)
attn_kernel(const float* __restrict__ p, float* __restrict__ out, int N) {
    // K tile: 64 keys x 64 dims bf16, hi (8KB) + lo (8KB), double buffered.
    __shared__ __align__(128) char sK[2][16384];
    __shared__ __align__(128) char sQ[16384];

    const int tid  = threadIdx.x;
    const int wid  = tid >> 5;
    const int lane = tid & 31;
    const int NT   = N / TN;                  // 256 tiles
    const uint32_t kbase[2] = { smem_u32(sK[0]), smem_u32(sK[1]) };
    const uint32_t qbase    = smem_u32(sQ);

    // ---- stage Q (this CTA's 64 rows, hi+lo) and K tile 0 via cp.async ----
    {
        const char* sph = (const char*)g_ph;
        const char* spl = (const char*)g_pl;
        const size_t qoff = (size_t)blockIdx.x * TM * D_DIM * 2;  // bytes
        #pragma unroll
        for (int r = 0; r < 4; r++) {
            int c = tid + r * NTH;                    // 512 chunks of 16B = 8KB
            uint32_t sw = SWZ(c * 16);
            CP16(qbase + sw,            sph + qoff + c * 16);
            CP16(qbase + 8192 + sw,     spl + qoff + c * 16);
            CP16(kbase[0] + sw,         sph + c * 16);
            CP16(kbase[0] + 8192 + sw,  spl + c * 16);
        }
        CP_COMMIT();
        CP_WAIT0();
        __syncthreads();
    }

    // ---- load Q fragments (A operand), hi and lo: [kb][4 regs] ----
    uint32_t qh[4][4], ql[4][4];
    {
        const int qrow  = wid * 16 + (lane & 7) + ((lane >> 3) & 1) * 8;
        const int qb16  = ((lane >> 4) & 1) * 16;
        #pragma unroll
        for (int kb = 0; kb < 4; kb++) {
            uint32_t off = SWZ((uint32_t)(qrow * 128 + kb * 32 + qb16));
            LDSM4(qh[kb][0], qh[kb][1], qh[kb][2], qh[kb][3], qbase + off);
            LDSM4(ql[kb][0], ql[kb][1], ql[kb][2], ql[kb][3], qbase + 8192 + off);
        }
    }

    float O[32];
    #pragma unroll
    for (int i = 0; i < 32; i++) O[i] = 0.f;
    float m0 = -1e30f, m1 = -1e30f, l0 = 0.f, l1 = 0.f;
    const float K1 = -5.770780163555854f;     // -4 * log2(e)

    // per-lane ldmatrix address components
    const uint32_t koffA = (uint32_t)((lane & 7) * 128 + (lane >> 3) * 16);   // QK B x4
    const int vrow  = (lane & 7) + ((lane >> 3) & 1) * 8;                      // PV B x4 trans
    const uint32_t vb16 = ((lane >> 4) & 1) * 16;

    const char* sph = (const char*)g_ph;
    const char* spl = (const char*)g_pl;

    for (int t = 0; t < NT; t++) {
        const uint32_t kb_ = kbase[t & 1];

        // prefetch next tile into other buffer
        if (t + 1 < NT) {
            const uint32_t nb_ = kbase[(t + 1) & 1];
            const size_t src = (size_t)(t + 1) * (TN * D_DIM * 2);
            #pragma unroll
            for (int r = 0; r < 4; r++) {
                int c = tid + r * NTH;
                uint32_t sw = SWZ(c * 16);
                CP16(nb_ + sw,        sph + src + c * 16);
                CP16(nb_ + 8192 + sw, spl + src + c * 16);
            }
        }
        CP_COMMIT();

        // ---- S = (QhKh + QhKl + QlKh), 16 rows x 64 keys per warp ----
        float S[32];
        #pragma unroll
        for (int i = 0; i < 32; i++) S[i] = 0.f;
        #pragma unroll
        for (int c = 0; c < 2; c++) {            // dim halves (32 dims each)
            #pragma unroll
            for (int nb = 0; nb < 8; nb++) {     // key blocks of 8
                uint32_t off = SWZ((uint32_t)(nb * 1024 + c * 64) + koffA);
                uint32_t f0, f1, f2, f3, g0, g1, g2, g3;
                LDSM4(f0, f1, f2, f3, kb_ + off);           // Kh: kb=2c, 2c+1
                mma16816(S + nb * 4, qh[2 * c],     f0, f1);
                mma16816(S + nb * 4, qh[2 * c + 1], f2, f3);
                mma16816(S + nb * 4, ql[2 * c],     f0, f1);
                mma16816(S + nb * 4, ql[2 * c + 1], f2, f3);
                LDSM4(g0, g1, g2, g3, kb_ + 8192 + off);    // Kl
                mma16816(S + nb * 4, qh[2 * c],     g0, g1);
                mma16816(S + nb * 4, qh[2 * c + 1], g2, g3);
            }
        }

        // ---- logits + online softmax ----
        float mc0 = -1e30f, mc1 = -1e30f;
        #pragma unroll
        for (int nb = 0; nb < 8; nb++) {
            S[nb * 4 + 0] *= K1;  S[nb * 4 + 1] *= K1;
            S[nb * 4 + 2] *= K1;  S[nb * 4 + 3] *= K1;
            mc0 = fmaxf(mc0, fmaxf(S[nb * 4 + 0], S[nb * 4 + 1]));
            mc1 = fmaxf(mc1, fmaxf(S[nb * 4 + 2], S[nb * 4 + 3]));
        }
        mc0 = fmaxf(mc0, __shfl_xor_sync(0xffffffffu, mc0, 1));
        mc0 = fmaxf(mc0, __shfl_xor_sync(0xffffffffu, mc0, 2));
        mc1 = fmaxf(mc1, __shfl_xor_sync(0xffffffffu, mc1, 1));
        mc1 = fmaxf(mc1, __shfl_xor_sync(0xffffffffu, mc1, 2));
        const float mn0 = fmaxf(m0, mc0), mn1 = fmaxf(m1, mc1);
        const float sc0 = ex2(m0 - mn0),  sc1 = ex2(m1 - mn1);
        m0 = mn0; m1 = mn1;
        float ls0 = 0.f, ls1 = 0.f;
        #pragma unroll
        for (int nb = 0; nb < 8; nb++) {
            float w0 = ex2(S[nb * 4 + 0] - m0);
            float w1 = ex2(S[nb * 4 + 1] - m0);
            float w2 = ex2(S[nb * 4 + 2] - m1);
            float w3 = ex2(S[nb * 4 + 3] - m1);
            S[nb * 4 + 0] = w0; S[nb * 4 + 1] = w1;
            S[nb * 4 + 2] = w2; S[nb * 4 + 3] = w3;
            ls0 += w0 + w1;  ls1 += w2 + w3;
        }
        l0 = l0 * sc0 + ls0;
        l1 = l1 * sc1 + ls1;
        #pragma unroll
        for (int nb = 0; nb < 8; nb++) {
            O[nb * 4 + 0] *= sc0;  O[nb * 4 + 1] *= sc0;
            O[nb * 4 + 2] *= sc1;  O[nb * 4 + 3] *= sc1;
        }

        // ---- O += P @ (Vh + Vl) ----
        #pragma unroll
        for (int kb = 0; kb < 4; kb++) {
            uint32_t pk0 = packbf(S[(2 * kb) * 4 + 0], S[(2 * kb) * 4 + 1]);
            uint32_t pk1 = packbf(S[(2 * kb) * 4 + 2], S[(2 * kb) * 4 + 3]);
            uint32_t pk2 = packbf(S[(2 * kb + 1) * 4 + 0], S[(2 * kb + 1) * 4 + 1]);
            uint32_t pk3 = packbf(S[(2 * kb + 1) * 4 + 2], S[(2 * kb + 1) * 4 + 3]);
            #pragma unroll
            for (int c = 0; c < 4; c++) {        // dim-pair blocks (16 dims each)
                uint32_t off = SWZ((uint32_t)((kb * 16 + vrow) * 128 + c * 32 + vb16));
                uint32_t f0, f1, f2, f3, g0, g1, g2, g3;
                LDSM4T(f0, f1, f2, f3, kb_ + off);          // Vh
                mma16816r(O + (2 * c) * 4,     pk0, pk1, pk2, pk3, f0, f1);
                mma16816r(O + (2 * c + 1) * 4, pk0, pk1, pk2, pk3, f2, f3);
                LDSM4T(g0, g1, g2, g3, kb_ + 8192 + off);   // Vl
                mma16816r(O + (2 * c) * 4,     pk0, pk1, pk2, pk3, g0, g1);
                mma16816r(O + (2 * c + 1) * 4, pk0, pk1, pk2, pk3, g2, g3);
            }
        }

        CP_WAIT0();
        __syncthreads();
    }

    // ---- epilogue ----
    l0 += __shfl_xor_sync(0xffffffffu, l0, 1);
    l0 += __shfl_xor_sync(0xffffffffu, l0, 2);
    l1 += __shfl_xor_sync(0xffffffffu, l1, 1);
    l1 += __shfl_xor_sync(0xffffffffu, l1, 2);
    const float i0 = 0.1f / l0, i1 = 0.1f / l1;
    const int r0 = blockIdx.x * TM + wid * 16 + (lane >> 2);
    const int r1 = r0 + 8;
    const int cb = (lane & 3) * 2;
    #pragma unroll
    for (int nb = 0; nb < 8; nb++) {
        const int col = nb * 8 + cb;
        float2 pv0 = *(const float2*)(p + (size_t)r0 * D_DIM + col);
        float2 pv1 = *(const float2*)(p + (size_t)r1 * D_DIM + col);
        float2 o0, o1;
        o0.x = 0.9f * pv0.x + O[nb * 4 + 0] * i0;
        o0.y = 0.9f * pv0.y + O[nb * 4 + 1] * i0;
        o1.x = 0.9f * pv1.x + O[nb * 4 + 2] * i1;
        o1.y = 0.9f * pv1.y + O[nb * 4 + 3] * i1;
        *(float2*)(out + (size_t)r0 * D_DIM + col) = o0;
        *(float2*)(out + (size_t)r1 * D_DIM + col) = o1;
    }
}

extern "C" void kernel_launch(void* const* d_in, const int* in_sizes, int n_in,
                              void* d_out, int out_size) {
    const float* p = (const float*)d_in[0];
    float* out = (float*)d_out;
    const int n = in_sizes[0];
    const int N = n / D_DIM;
    prep_kernel<<<(n + 255) / 256, 256>>>(p, n);
    attn_kernel<<<N / TM, NTH>>>(p, out, N);
}

// round 5
// speedup vs baseline: 46.6922x; 1.1711x over previous
#include <cuda_runtime.h>
#include <cuda_fp16.h>
#include <cstdint>

// out = 0.9*p + 0.1 * softmax(-4 p p^T) p    N=16384, D=64, fp32
// FA2-style flash attention, fp16 hi/lo QK (3 passes), fp16 single-pass PV.

#define D_DIM 64
#define TM    64
#define TN    64
#define NTH   128
#define PN    (16384*64)
#define QSCALE 5.770780163555854f   // 4*log2(e)

__device__ __half g_qh[PN];   // fp16(QSCALE*p)
__device__ __half g_ql[PN];   // residual
__device__ __half g_ph[PN];   // fp16(p)        (K hi / V)
__device__ __half g_pl[PN];   // residual       (K lo)

__device__ __forceinline__ uint32_t smem_u32(const void* p) {
    uint32_t a;
    asm("{ .reg .u64 t; cvta.to.shared.u64 t, %1; cvt.u32.u64 %0, t; }" : "=r"(a) : "l"(p));
    return a;
}
#define SWZ(x) ((x) ^ (((x) >> 3) & 0x70))

#define CP16(dst, src) asm volatile("cp.async.ca.shared.global [%0], [%1], 16;" :: "r"(dst), "l"(src))
#define CP_COMMIT()    asm volatile("cp.async.commit_group;" ::: "memory")
#define CP_WAIT0()     asm volatile("cp.async.wait_group 0;" ::: "memory")

#define LDSM4(r0, r1, r2, r3, a) \
    asm volatile("ldmatrix.sync.aligned.m8n8.x4.shared.b16 {%0,%1,%2,%3}, [%4];" \
        : "=r"(r0), "=r"(r1), "=r"(r2), "=r"(r3) : "r"(a))
#define LDSM4T(r0, r1, r2, r3, a) \
    asm volatile("ldmatrix.sync.aligned.m8n8.x4.trans.shared.b16 {%0,%1,%2,%3}, [%4];" \
        : "=r"(r0), "=r"(r1), "=r"(r2), "=r"(r3) : "r"(a))

__device__ __forceinline__ void mma16816(float* c, const uint32_t a[4], uint32_t b0, uint32_t b1) {
    asm volatile("mma.sync.aligned.m16n8k16.row.col.f32.f16.f16.f32 "
        "{%0,%1,%2,%3},{%4,%5,%6,%7},{%8,%9},{%0,%1,%2,%3};"
        : "+f"(c[0]), "+f"(c[1]), "+f"(c[2]), "+f"(c[3])
        : "r"(a[0]), "r"(a[1]), "r"(a[2]), "r"(a[3]), "r"(b0), "r"(b1));
}
__device__ __forceinline__ void mma16816r(float* c, uint32_t a0, uint32_t a1, uint32_t a2, uint32_t a3,
                                          uint32_t b0, uint32_t b1) {
    asm volatile("mma.sync.aligned.m16n8k16.row.col.f32.f16.f16.f32 "
        "{%0,%1,%2,%3},{%4,%5,%6,%7},{%8,%9},{%0,%1,%2,%3};"
        : "+f"(c[0]), "+f"(c[1]), "+f"(c[2]), "+f"(c[3])
        : "r"(a0), "r"(a1), "r"(a2), "r"(a3), "r"(b0), "r"(b1));
}
__device__ __forceinline__ float ex2(float x) {
    float r; asm("ex2.approx.ftz.f32 %0, %1;" : "=f"(r) : "f"(x)); return r;
}
__device__ __forceinline__ uint32_t packh(float lo, float hi) {
    uint32_t r; asm("cvt.rn.f16x2.f32 %0, %2, %1;" : "=r"(r) : "f"(lo), "f"(hi)); return r;
}

__global__ void prep_kernel(const float* __restrict__ p, int n) {
    int i = blockIdx.x * blockDim.x + threadIdx.x;
    if (i < n) {
        float x = p[i];
        __half h = __float2half_rn(x);
        g_ph[i] = h;
        g_pl[i] = __float2half_rn(x - __half2float(h));
        float xs = QSCALE * x;
        __half qh = __float2half_rn(xs);
        g_qh[i] = qh;
        g_ql[i] = __float2half_rn(xs - __half2float(qh));
    }
}

__global__ void __launch_bounds__(NTH, 2)
attn_kernel(const float* __restrict__ p, float* __restrict__ out, int N) {
    __shared__ __align__(128) char sK[2][16384];   // Kh(8K)+Kl(8K), double buffered
    __shared__ __align__(128) char sQ[16384];      // Qh(8K)+Ql(8K)

    const int tid  = threadIdx.x;
    const int wid  = tid >> 5;
    const int lane = tid & 31;
    const int NT   = N / TN;
    const uint32_t kbase[2] = { smem_u32(sK[0]), smem_u32(sK[1]) };
    const uint32_t qbase    = smem_u32(sQ);

    {   // stage Q (scaled hi/lo) and K tile 0 (hi/lo)
        const char* sqh = (const char*)g_qh;
        const char* sql = (const char*)g_ql;
        const char* sph = (const char*)g_ph;
        const char* spl = (const char*)g_pl;
        const size_t qoff = (size_t)blockIdx.x * TM * D_DIM * 2;
        #pragma unroll
        for (int r = 0; r < 4; r++) {
            int c = tid + r * NTH;
            uint32_t sw = SWZ(c * 16);
            CP16(qbase + sw,           sqh + qoff + c * 16);
            CP16(qbase + 8192 + sw,    sql + qoff + c * 16);
            CP16(kbase[0] + sw,        sph + c * 16);
            CP16(kbase[0] + 8192 + sw, spl + c * 16);
        }
        CP_COMMIT();
        CP_WAIT0();
        __syncthreads();
    }

    uint32_t qh[4][4], ql[4][4];
    {
        const int qrow = wid * 16 + (lane & 7) + ((lane >> 3) & 1) * 8;
        const int qb16 = ((lane >> 4) & 1) * 16;
        #pragma unroll
        for (int kb = 0; kb < 4; kb++) {
            uint32_t off = SWZ((uint32_t)(qrow * 128 + kb * 32 + qb16));
            LDSM4(qh[kb][0], qh[kb][1], qh[kb][2], qh[kb][3], qbase + off);
            LDSM4(ql[kb][0], ql[kb][1], ql[kb][2], ql[kb][3], qbase + 8192 + off);
        }
    }

    float O[32];
    #pragma unroll
    for (int i = 0; i < 32; i++) O[i] = 0.f;
    // T = QSCALE * q.k ; logit = -T ; track running MIN of T.
    float m0 = 1e30f, m1 = 1e30f, l0 = 0.f, l1 = 0.f;

    const uint32_t koffA = (uint32_t)((lane & 7) * 128 + (lane >> 3) * 16);
    const int vrow  = (lane & 7) + ((lane >> 3) & 1) * 8;
    const uint32_t vb16 = ((lane >> 4) & 1) * 16;

    const char* sph = (const char*)g_ph;
    const char* spl = (const char*)g_pl;

    for (int t = 0; t < NT; t++) {
        const uint32_t kb_ = kbase[t & 1];

        if (t + 1 < NT) {
            const uint32_t nb_ = kbase[(t + 1) & 1];
            const size_t src = (size_t)(t + 1) * (TN * D_DIM * 2);
            #pragma unroll
            for (int r = 0; r < 4; r++) {
                int c = tid + r * NTH;
                uint32_t sw = SWZ(c * 16);
                CP16(nb_ + sw,        sph + src + c * 16);
                CP16(nb_ + 8192 + sw, spl + src + c * 16);
            }
        }
        CP_COMMIT();

        // ---- T = QhKh + QhKl + QlKh (scaled scores) ----
        float S[32];
        #pragma unroll
        for (int i = 0; i < 32; i++) S[i] = 0.f;
        #pragma unroll
        for (int c = 0; c < 2; c++) {
            #pragma unroll
            for (int nb = 0; nb < 8; nb++) {
                uint32_t off = SWZ((uint32_t)(nb * 1024 + c * 64) + koffA);
                uint32_t f0, f1, f2, f3, g0, g1, g2, g3;
                LDSM4(f0, f1, f2, f3, kb_ + off);            // Kh
                mma16816(S + nb * 4, qh[2 * c],     f0, f1);
                mma16816(S + nb * 4, qh[2 * c + 1], f2, f3);
                mma16816(S + nb * 4, ql[2 * c],     f0, f1);
                mma16816(S + nb * 4, ql[2 * c + 1], f2, f3);
                LDSM4(g0, g1, g2, g3, kb_ + 8192 + off);     // Kl
                mma16816(S + nb * 4, qh[2 * c],     g0, g1);
                mma16816(S + nb * 4, qh[2 * c + 1], g2, g3);
            }
        }

        // ---- online softmax on logits = -T (min-tracking) ----
        float mc0 = 1e30f, mc1 = 1e30f;
        #pragma unroll
        for (int nb = 0; nb < 8; nb++) {
            mc0 = fminf(mc0, fminf(S[nb * 4 + 0], S[nb * 4 + 1]));
            mc1 = fminf(mc1, fminf(S[nb * 4 + 2], S[nb * 4 + 3]));
        }
        mc0 = fminf(mc0, __shfl_xor_sync(0xffffffffu, mc0, 1));
        mc0 = fminf(mc0, __shfl_xor_sync(0xffffffffu, mc0, 2));
        mc1 = fminf(mc1, __shfl_xor_sync(0xffffffffu, mc1, 1));
        mc1 = fminf(mc1, __shfl_xor_sync(0xffffffffu, mc1, 2));
        const float mn0 = fminf(m0, mc0), mn1 = fminf(m1, mc1);
        const bool upd = (mn0 < m0) | (mn1 < m1);
        if (__any_sync(0xffffffffu, upd)) {
            const float sc0 = ex2(mn0 - m0), sc1 = ex2(mn1 - m1);
            l0 *= sc0;  l1 *= sc1;
            #pragma unroll
            for (int nb = 0; nb < 8; nb++) {
                O[nb * 4 + 0] *= sc0;  O[nb * 4 + 1] *= sc0;
                O[nb * 4 + 2] *= sc1;  O[nb * 4 + 3] *= sc1;
            }
            m0 = mn0;  m1 = mn1;
        }
        float ls0 = 0.f, ls1 = 0.f;
        #pragma unroll
        for (int nb = 0; nb < 8; nb++) {
            float w0 = ex2(m0 - S[nb * 4 + 0]);
            float w1 = ex2(m0 - S[nb * 4 + 1]);
            float w2 = ex2(m1 - S[nb * 4 + 2]);
            float w3 = ex2(m1 - S[nb * 4 + 3]);
            S[nb * 4 + 0] = w0; S[nb * 4 + 1] = w1;
            S[nb * 4 + 2] = w2; S[nb * 4 + 3] = w3;
            ls0 += w0 + w1;  ls1 += w2 + w3;
        }
        l0 += ls0;  l1 += ls1;

        // ---- O += P @ Vh (single fp16 pass) ----
        #pragma unroll
        for (int kb = 0; kb < 4; kb++) {
            uint32_t pk0 = packh(S[(2 * kb) * 4 + 0], S[(2 * kb) * 4 + 1]);
            uint32_t pk1 = packh(S[(2 * kb) * 4 + 2], S[(2 * kb) * 4 + 3]);
            uint32_t pk2 = packh(S[(2 * kb + 1) * 4 + 0], S[(2 * kb + 1) * 4 + 1]);
            uint32_t pk3 = packh(S[(2 * kb + 1) * 4 + 2], S[(2 * kb + 1) * 4 + 3]);
            #pragma unroll
            for (int c = 0; c < 4; c++) {
                uint32_t off = SWZ((uint32_t)((kb * 16 + vrow) * 128 + c * 32 + vb16));
                uint32_t f0, f1, f2, f3;
                LDSM4T(f0, f1, f2, f3, kb_ + off);           // Vh
                mma16816r(O + (2 * c) * 4,     pk0, pk1, pk2, pk3, f0, f1);
                mma16816r(O + (2 * c + 1) * 4, pk0, pk1, pk2, pk3, f2, f3);
            }
        }

        CP_WAIT0();
        __syncthreads();
    }

    // ---- epilogue ----
    l0 += __shfl_xor_sync(0xffffffffu, l0, 1);
    l0 += __shfl_xor_sync(0xffffffffu, l0, 2);
    l1 += __shfl_xor_sync(0xffffffffu, l1, 1);
    l1 += __shfl_xor_sync(0xffffffffu, l1, 2);
    const float i0 = 0.1f / l0, i1 = 0.1f / l1;
    const int r0 = blockIdx.x * TM + wid * 16 + (lane >> 2);
    const int r1 = r0 + 8;
    const int cb = (lane & 3) * 2;
    #pragma unroll
    for (int nb = 0; nb < 8; nb++) {
        const int col = nb * 8 + cb;
        float2 pv0 = *(const float2*)(p + (size_t)r0 * D_DIM + col);
        float2 pv1 = *(const float2*)(p + (size_t)r1 * D_DIM + col);
        float2 o0, o1;
        o0.x = 0.9f * pv0.x + O[nb * 4 + 0] * i0;
        o0.y = 0.9f * pv0.y + O[nb * 4 + 1] * i0;
        o1.x = 0.9f * pv1.x + O[nb * 4 + 2] * i1;
        o1.y = 0.9f * pv1.y + O[nb * 4 + 3] * i1;
        *(float2*)(out + (size_t)r0 * D_DIM + col) = o0;
        *(float2*)(out + (size_t)r1 * D_DIM + col) = o1;
    }
}

extern "C" void kernel_launch(void* const* d_in, const int* in_sizes, int n_in,
                              void* d_out, int out_size) {
    const float* p = (const float*)d_in[0];
    float* out = (float*)d_out;
    const int n = in_sizes[0];
    const int N = n / D_DIM;
    prep_kernel<<<(n + 255) / 256, 256>>>(p, n);
    attn_kernel<<<N / TM, NTH>>>(p, out, N);
}